// round 4
// baseline (speedup 1.0000x reference)
#include <cuda_runtime.h>
#include <math.h>

#define N_NODES 50000
#define N_EDGES 500000
#define F 128
#define R 8

// ---------------- scratch (device globals; no allocations allowed) ----------
__device__ float g_xw[(size_t)R * N_NODES * F];   // 204.8 MB: per-relation projected feats
__device__ float g_h1[(size_t)N_NODES * F];       // layer-1 output / layer-2 input
__device__ float g_aq[R * N_NODES];
__device__ float g_ak[R * N_NODES];
__device__ float g_u[R * F];
__device__ float g_v[R * F];
__device__ float g_m[N_NODES];
__device__ float g_den[N_NODES];
__device__ float g_lg[N_EDGES];
__device__ float g_e[N_EDGES];

// ---------------- helpers ----------------
__device__ __forceinline__ void atomicMaxF(float* a, float v) {
    // order-preserving int mapping for IEEE floats
    if (v >= 0.0f) atomicMax((int*)a, __float_as_int(v));
    else           atomicMin((unsigned int*)a, (unsigned int)__float_as_int(v));
}

__device__ __forceinline__ void red_add_v4(float* addr, float4 v) {
    asm volatile("red.global.add.v4.f32 [%0], {%1, %2, %3, %4};"
                 :: "l"(addr), "f"(v.x), "f"(v.y), "f"(v.z), "f"(v.w)
                 : "memory");
}

// ---------------- kernels ----------------

// zero agg buffer; init m=-inf, den=0
__global__ void k_init(float* __restrict__ agg) {
    int i = blockIdx.x * blockDim.x + threadIdx.x;
    if (i < N_NODES * F) agg[i] = 0.0f;
    if (i < N_NODES) { g_m[i] = __int_as_float(0xff800000); g_den[i] = 0.0f; }
}

// u_r = W_r q, v_r = W_r k  (per layer)
__global__ void k_uv(const float* __restrict__ Wl, const float* __restrict__ q,
                     const float* __restrict__ kv) {
    __shared__ float qs[F], ks[F];
    int r = blockIdx.x, f = threadIdx.x;
    qs[f] = q[f]; ks[f] = kv[f];
    __syncthreads();
    const float* Wr = Wl + ((size_t)r * F + f) * F;
    float su = 0.f, sv = 0.f;
#pragma unroll 8
    for (int g = 0; g < F; g++) { float w = Wr[g]; su += w * qs[g]; sv += w * ks[g]; }
    g_u[r * F + f] = su;
    g_v[r * F + f] = sv;
}

// xw[r] = h @ W_r   (BM=128, BN=128, BK=32, 256 threads, 8x8 micro-tile)
__global__ void __launch_bounds__(256) k_gemm(const float* __restrict__ h,
                                              const float* __restrict__ Wl) {
    __shared__ float Hs[128][33];
    __shared__ float Ws[32][129];
    const int r  = blockIdx.y;
    const int n0 = blockIdx.x * 128;
    const int tid = threadIdx.x;
    const int tx = tid & 15, ty = tid >> 4;
    const float* Wr = Wl + (size_t)r * F * F;

    float acc[8][8];
#pragma unroll
    for (int i = 0; i < 8; i++)
#pragma unroll
        for (int j = 0; j < 8; j++) acc[i][j] = 0.f;

    for (int kt = 0; kt < F; kt += 32) {
        // H tile: 128 rows x 32 cols
#pragma unroll
        for (int i = 0; i < 4; i++) {
            int t = tid + i * 256;          // 0..1023
            int row = t >> 3, q4 = t & 7;   // q4: float4 index within 32 cols
            int gn = n0 + row;
            float4 val = make_float4(0.f, 0.f, 0.f, 0.f);
            if (gn < N_NODES)
                val = *(const float4*)(h + (size_t)gn * F + kt + q4 * 4);
            Hs[row][q4 * 4 + 0] = val.x; Hs[row][q4 * 4 + 1] = val.y;
            Hs[row][q4 * 4 + 2] = val.z; Hs[row][q4 * 4 + 3] = val.w;
        }
        // W tile: 32 rows x 128 cols
#pragma unroll
        for (int i = 0; i < 4; i++) {
            int t = tid + i * 256;
            int kk = t >> 5, q4 = t & 31;
            float4 val = *(const float4*)(Wr + (size_t)(kt + kk) * F + q4 * 4);
            Ws[kk][q4 * 4 + 0] = val.x; Ws[kk][q4 * 4 + 1] = val.y;
            Ws[kk][q4 * 4 + 2] = val.z; Ws[kk][q4 * 4 + 3] = val.w;
        }
        __syncthreads();
#pragma unroll 8
        for (int kk = 0; kk < 32; kk++) {
            float a[8], b[8];
#pragma unroll
            for (int ii = 0; ii < 8; ii++) a[ii] = Hs[ty + ii * 16][kk];
#pragma unroll
            for (int jj = 0; jj < 8; jj++) b[jj] = Ws[kk][tx + jj * 16];
#pragma unroll
            for (int ii = 0; ii < 8; ii++)
#pragma unroll
                for (int jj = 0; jj < 8; jj++) acc[ii][jj] += a[ii] * b[jj];
        }
        __syncthreads();
    }

    float* out = g_xw + (size_t)r * N_NODES * F;
#pragma unroll
    for (int ii = 0; ii < 8; ii++) {
        int gn = n0 + ty + ii * 16;
        if (gn < N_NODES) {
#pragma unroll
            for (int jj = 0; jj < 8; jj++)
                out[(size_t)gn * F + tx + jj * 16] = acc[ii][jj];
        }
    }
}

// aq[r,n] = h_n . u_r ; ak[r,n] = h_n . v_r   (one warp per node)
__global__ void k_aqak(const float* __restrict__ h) {
    __shared__ float us[R * F], vs[R * F];
    int tid = threadIdx.x;
    for (int i = tid; i < R * F; i += blockDim.x) { us[i] = g_u[i]; vs[i] = g_v[i]; }
    __syncthreads();
    int gidx = blockIdx.x * blockDim.x + tid;
    int n = gidx >> 5, lane = gidx & 31;
    if (n >= N_NODES) return;
    float4 hv = ((const float4*)h)[(size_t)n * 32 + lane];
#pragma unroll
    for (int r = 0; r < R; r++) {
        const float* u = us + r * F + lane * 4;
        const float* v = vs + r * F + lane * 4;
        float s = hv.x * u[0] + hv.y * u[1] + hv.z * u[2] + hv.w * u[3];
        float t = hv.x * v[0] + hv.y * v[1] + hv.z * v[2] + hv.w * v[3];
#pragma unroll
        for (int o = 16; o; o >>= 1) {
            s += __shfl_xor_sync(0xffffffffu, s, o);
            t += __shfl_xor_sync(0xffffffffu, t, o);
        }
        if (lane == 0) { g_aq[r * N_NODES + n] = s; g_ak[r * N_NODES + n] = t; }
    }
}

// per-edge logits + segment max
__global__ void k_logit(const int* __restrict__ ei, const int* __restrict__ et) {
    int e = blockIdx.x * blockDim.x + threadIdx.x;
    if (e >= N_EDGES) return;
    int s = ei[e], d = ei[N_EDGES + e], r = et[e];
    float lg = g_aq[r * N_NODES + d] + g_ak[r * N_NODES + s];
    lg = lg > 0.f ? lg : 0.2f * lg;   // leaky_relu
    g_lg[e] = lg;
    atomicMaxF(&g_m[d], lg);
}

// e = exp(logit - m[dst]); denom[dst] += e
__global__ void k_exp(const int* __restrict__ ei) {
    int e = blockIdx.x * blockDim.x + threadIdx.x;
    if (e >= N_EDGES) return;
    int d = ei[N_EDGES + e];
    float ex = expf(g_lg[e] - g_m[d]);
    g_e[e] = ex;
    atomicAdd(&g_den[d], ex);
}

// agg[dst,:] += e * xw[rt, src, :]   (one warp per edge, v4 reductions)
__global__ void k_agg(const int* __restrict__ ei, const int* __restrict__ et,
                      float* __restrict__ agg) {
    int gidx = blockIdx.x * blockDim.x + threadIdx.x;
    int e = gidx >> 5, lane = gidx & 31;
    if (e >= N_EDGES) return;
    int s = ei[e], d = ei[N_EDGES + e], r = et[e];
    float w = g_e[e];
    const float4* xs = (const float4*)(g_xw + ((size_t)r * N_NODES + s) * F);
    float* ad = agg + (size_t)d * F + lane * 4;
    float4 v = xs[lane];
    v.x *= w; v.y *= w; v.z *= w; v.w *= w;
    red_add_v4(ad, v);
}

// out = relu(agg / (den + 1e-16) + bias)
__global__ void k_fin(const float* __restrict__ agg, const float* __restrict__ bias,
                      float* __restrict__ out) {
    int i = blockIdx.x * blockDim.x + threadIdx.x;
    if (i >= N_NODES * F) return;
    int n = i >> 7, f = i & 127;
    float v = agg[i] / (g_den[n] + 1e-16f) + bias[f];
    out[i] = v > 0.f ? v : 0.f;
}

// ---------------- launch ----------------
extern "C" void kernel_launch(void* const* d_in, const int* in_sizes, int n_in,
                              void* d_out, int out_size) {
    const float* x    = (const float*)d_in[0];
    const float* W    = (const float*)d_in[1];
    const float* attq = (const float*)d_in[2];
    const float* attk = (const float*)d_in[3];
    const float* bias = (const float*)d_in[4];
    const int*   ei   = (const int*)d_in[5];
    const int*   et   = (const int*)d_in[6];
    float* out = (float*)d_out;

    const int NF = N_NODES * F;
    float* h1_ptr = nullptr;
    cudaGetSymbolAddress((void**)&h1_ptr, g_h1);

    for (int l = 0; l < 2; l++) {
        const float* h    = (l == 0) ? x : h1_ptr;
        float*       aggp = (l == 0) ? h1_ptr : out;   // in-place finalize
        const float* Wl   = W + (size_t)l * R * F * F;
        const float* ql   = attq + (size_t)l * F;
        const float* kl   = attk + (size_t)l * F;
        const float* bl   = bias + (size_t)l * F;

        k_init <<<(NF + 255) / 256, 256>>>(aggp);
        k_uv   <<<R, F>>>(Wl, ql, kl);
        k_gemm <<<dim3((N_NODES + 127) / 128, R), 256>>>(h, Wl);
        k_aqak <<<(N_NODES * 32 + 255) / 256, 256>>>(h);
        k_logit<<<(N_EDGES + 255) / 256, 256>>>(ei, et);
        k_exp  <<<(N_EDGES + 255) / 256, 256>>>(ei);
        k_agg  <<<(N_EDGES * 32 + 255) / 256, 256>>>(ei, et, aggp);
        k_fin  <<<(NF + 255) / 256, 256>>>(aggp, bl, aggp);
    }
}

// round 5
// speedup vs baseline: 1.7355x; 1.7355x over previous
#include <cuda_runtime.h>
#include <math.h>

#define N_NODES 50000
#define N_EDGES 500000
#define F 128
#define R 8

// ---------------- scratch (device globals; no allocations allowed) ----------
__device__ float g_xw[(size_t)R * N_NODES * F];   // 204.8 MB: per-relation projected feats
__device__ float g_h1[(size_t)N_NODES * F];       // layer-1 output / layer-2 input
__device__ float g_aq[R * N_NODES];
__device__ float g_ak[R * N_NODES];
__device__ float g_u[R * F];
__device__ float g_v[R * F];
__device__ float g_m[N_NODES];
__device__ float g_den[N_NODES];
__device__ float g_lg[N_EDGES];
__device__ float g_e[N_EDGES];

// ---------------- helpers ----------------
__device__ __forceinline__ void atomicMaxF(float* a, float v) {
    if (v >= 0.0f) atomicMax((int*)a, __float_as_int(v));
    else           atomicMin((unsigned int*)a, (unsigned int)__float_as_int(v));
}

__device__ __forceinline__ void red_add_v4(float* addr, float4 v) {
    asm volatile("red.global.add.v4.f32 [%0], {%1, %2, %3, %4};"
                 :: "l"(addr), "f"(v.x), "f"(v.y), "f"(v.z), "f"(v.w)
                 : "memory");
}

__device__ __forceinline__ float cvt_tf32(float x) {
    unsigned int o;
    asm("cvt.rna.tf32.f32 %0, %1;" : "=r"(o) : "f"(x));
    return __uint_as_float(o);
}

__device__ __forceinline__ void mma_tf32(float* c, const float* a, const float* b) {
    asm volatile(
        "mma.sync.aligned.m16n8k8.row.col.f32.tf32.tf32.f32 "
        "{%0,%1,%2,%3}, {%4,%5,%6,%7}, {%8,%9}, {%0,%1,%2,%3};"
        : "+f"(c[0]), "+f"(c[1]), "+f"(c[2]), "+f"(c[3])
        : "r"(__float_as_uint(a[0])), "r"(__float_as_uint(a[1])),
          "r"(__float_as_uint(a[2])), "r"(__float_as_uint(a[3])),
          "r"(__float_as_uint(b[0])), "r"(__float_as_uint(b[1])));
}

// ---------------- kernels ----------------

__global__ void k_init(float* __restrict__ agg) {
    int i = blockIdx.x * blockDim.x + threadIdx.x;
    if (i < N_NODES * F) agg[i] = 0.0f;
    if (i < N_NODES) { g_m[i] = __int_as_float(0xff800000); g_den[i] = 0.0f; }
}

// u_r = W_r q, v_r = W_r k  (per layer)
__global__ void k_uv(const float* __restrict__ Wl, const float* __restrict__ q,
                     const float* __restrict__ kv) {
    __shared__ float qs[F], ks[F];
    int r = blockIdx.x, f = threadIdx.x;
    qs[f] = q[f]; ks[f] = kv[f];
    __syncthreads();
    const float* Wr = Wl + ((size_t)r * F + f) * F;
    float su = 0.f, sv = 0.f;
#pragma unroll 8
    for (int g = 0; g < F; g++) { float w = Wr[g]; su += w * qs[g]; sv += w * ks[g]; }
    g_u[r * F + f] = su;
    g_v[r * F + f] = sv;
}

// xw[r] = h @ W_r via tf32 mma.sync  (BM=128, BN=128, BK=32, 8 warps 4x2)
__global__ void __launch_bounds__(256) k_gemm(const float* __restrict__ h,
                                              const float* __restrict__ Wl) {
    __shared__ float Hs[128][36];   // bank = (4*row + col) % 32 -> conflict-free A frags
    __shared__ float Ws[32][136];   // bank = (8*row + col) % 32 -> conflict-free B frags
    const int r   = blockIdx.y;
    const int n0  = blockIdx.x * 128;
    const int tid = threadIdx.x;
    const int lane = tid & 31, wid = tid >> 5;
    const int warp_m = wid & 3;      // 4 warps over M (32 rows each)
    const int warp_n = wid >> 2;     // 2 warps over N (64 cols each)
    const float* Wr = Wl + (size_t)r * F * F;

    float c[2][8][4];
#pragma unroll
    for (int mt = 0; mt < 2; mt++)
#pragma unroll
        for (int nt = 0; nt < 8; nt++)
#pragma unroll
            for (int i = 0; i < 4; i++) c[mt][nt][i] = 0.f;

    for (int kt = 0; kt < F; kt += 32) {
        // H tile: 128 rows x 32 cols (convert to tf32 on store)
#pragma unroll
        for (int i = 0; i < 4; i++) {
            int t = tid + i * 256;
            int row = t >> 3, q4 = t & 7;
            int gn = n0 + row;
            float4 v = make_float4(0.f, 0.f, 0.f, 0.f);
            if (gn < N_NODES)
                v = *(const float4*)(h + (size_t)gn * F + kt + q4 * 4);
            Hs[row][q4 * 4 + 0] = cvt_tf32(v.x); Hs[row][q4 * 4 + 1] = cvt_tf32(v.y);
            Hs[row][q4 * 4 + 2] = cvt_tf32(v.z); Hs[row][q4 * 4 + 3] = cvt_tf32(v.w);
        }
        // W tile: 32 rows x 128 cols
#pragma unroll
        for (int i = 0; i < 4; i++) {
            int t = tid + i * 256;
            int kk = t >> 5, q4 = t & 31;
            float4 v = *(const float4*)(Wr + (size_t)(kt + kk) * F + q4 * 4);
            Ws[kk][q4 * 4 + 0] = cvt_tf32(v.x); Ws[kk][q4 * 4 + 1] = cvt_tf32(v.y);
            Ws[kk][q4 * 4 + 2] = cvt_tf32(v.z); Ws[kk][q4 * 4 + 3] = cvt_tf32(v.w);
        }
        __syncthreads();

#pragma unroll
        for (int ks = 0; ks < 4; ks++) {
            const int k0 = ks * 8;
            float a[2][4];
#pragma unroll
            for (int mt = 0; mt < 2; mt++) {
                int row = warp_m * 32 + mt * 16 + (lane >> 2);
                int col = k0 + (lane & 3);
                a[mt][0] = Hs[row][col];
                a[mt][1] = Hs[row + 8][col];
                a[mt][2] = Hs[row][col + 4];
                a[mt][3] = Hs[row + 8][col + 4];
            }
            float b[8][2];
#pragma unroll
            for (int nt = 0; nt < 8; nt++) {
                int brow = k0 + (lane & 3);
                int bcol = warp_n * 64 + nt * 8 + (lane >> 2);
                b[nt][0] = Ws[brow][bcol];
                b[nt][1] = Ws[brow + 4][bcol];
            }
#pragma unroll
            for (int mt = 0; mt < 2; mt++)
#pragma unroll
                for (int nt = 0; nt < 8; nt++)
                    mma_tf32(c[mt][nt], a[mt], b[nt]);
        }
        __syncthreads();
    }

    // epilogue: c[mt][nt] rows = {base, base+8}, cols = 2*(lane&3), +1
    float* out = g_xw + (size_t)r * N_NODES * F;
#pragma unroll
    for (int mt = 0; mt < 2; mt++) {
        int row0 = warp_m * 32 + mt * 16 + (lane >> 2);
#pragma unroll
        for (int half = 0; half < 2; half++) {
            int gn = n0 + row0 + half * 8;
            if (gn < N_NODES) {
#pragma unroll
                for (int nt = 0; nt < 8; nt++) {
                    int col = warp_n * 64 + nt * 8 + 2 * (lane & 3);
                    float2 val;
                    val.x = c[mt][nt][half * 2 + 0];
                    val.y = c[mt][nt][half * 2 + 1];
                    *(float2*)(out + (size_t)gn * F + col) = val;
                }
            }
        }
    }
}

// aq[r,n] = h_n . u_r ; ak[r,n] = h_n . v_r   (one warp per node)
__global__ void k_aqak(const float* __restrict__ h) {
    __shared__ float us[R * F], vs[R * F];
    int tid = threadIdx.x;
    for (int i = tid; i < R * F; i += blockDim.x) { us[i] = g_u[i]; vs[i] = g_v[i]; }
    __syncthreads();
    int gidx = blockIdx.x * blockDim.x + tid;
    int n = gidx >> 5, lane = gidx & 31;
    if (n >= N_NODES) return;
    float4 hv = ((const float4*)h)[(size_t)n * 32 + lane];
#pragma unroll
    for (int r = 0; r < R; r++) {
        const float* u = us + r * F + lane * 4;
        const float* v = vs + r * F + lane * 4;
        float s = hv.x * u[0] + hv.y * u[1] + hv.z * u[2] + hv.w * u[3];
        float t = hv.x * v[0] + hv.y * v[1] + hv.z * v[2] + hv.w * v[3];
#pragma unroll
        for (int o = 16; o; o >>= 1) {
            s += __shfl_xor_sync(0xffffffffu, s, o);
            t += __shfl_xor_sync(0xffffffffu, t, o);
        }
        if (lane == 0) { g_aq[r * N_NODES + n] = s; g_ak[r * N_NODES + n] = t; }
    }
}

// per-edge logits + segment max
__global__ void k_logit(const int* __restrict__ ei, const int* __restrict__ et) {
    int e = blockIdx.x * blockDim.x + threadIdx.x;
    if (e >= N_EDGES) return;
    int s = ei[e], d = ei[N_EDGES + e], r = et[e];
    float lg = g_aq[r * N_NODES + d] + g_ak[r * N_NODES + s];
    lg = lg > 0.f ? lg : 0.2f * lg;   // leaky_relu
    g_lg[e] = lg;
    atomicMaxF(&g_m[d], lg);
}

// e = exp(logit - m[dst]); denom[dst] += e
__global__ void k_exp(const int* __restrict__ ei) {
    int e = blockIdx.x * blockDim.x + threadIdx.x;
    if (e >= N_EDGES) return;
    int d = ei[N_EDGES + e];
    float ex = expf(g_lg[e] - g_m[d]);
    g_e[e] = ex;
    atomicAdd(&g_den[d], ex);
}

// agg[dst,:] += e * xw[rt, src, :]   (one warp per edge, v4 reductions)
__global__ void k_agg(const int* __restrict__ ei, const int* __restrict__ et,
                      float* __restrict__ agg) {
    int gidx = blockIdx.x * blockDim.x + threadIdx.x;
    int e = gidx >> 5, lane = gidx & 31;
    if (e >= N_EDGES) return;
    int s = ei[e], d = ei[N_EDGES + e], r = et[e];
    float w = g_e[e];
    const float4* xs = (const float4*)(g_xw + ((size_t)r * N_NODES + s) * F);
    float* ad = agg + (size_t)d * F + lane * 4;
    float4 v = xs[lane];
    v.x *= w; v.y *= w; v.z *= w; v.w *= w;
    red_add_v4(ad, v);
}

// out = relu(agg / (den + 1e-16) + bias)
__global__ void k_fin(const float* __restrict__ agg, const float* __restrict__ bias,
                      float* __restrict__ out) {
    int i = blockIdx.x * blockDim.x + threadIdx.x;
    if (i >= N_NODES * F) return;
    int n = i >> 7, f = i & 127;
    float v = agg[i] / (g_den[n] + 1e-16f) + bias[f];
    out[i] = v > 0.f ? v : 0.f;
}

// ---------------- launch ----------------
extern "C" void kernel_launch(void* const* d_in, const int* in_sizes, int n_in,
                              void* d_out, int out_size) {
    const float* x    = (const float*)d_in[0];
    const float* W    = (const float*)d_in[1];
    const float* attq = (const float*)d_in[2];
    const float* attk = (const float*)d_in[3];
    const float* bias = (const float*)d_in[4];
    const int*   ei   = (const int*)d_in[5];
    const int*   et   = (const int*)d_in[6];
    float* out = (float*)d_out;

    const int NF = N_NODES * F;
    float* h1_ptr = nullptr;
    cudaGetSymbolAddress((void**)&h1_ptr, g_h1);

    for (int l = 0; l < 2; l++) {
        const float* h    = (l == 0) ? x : h1_ptr;
        float*       aggp = (l == 0) ? h1_ptr : out;   // in-place finalize
        const float* Wl   = W + (size_t)l * R * F * F;
        const float* ql   = attq + (size_t)l * F;
        const float* kl   = attk + (size_t)l * F;
        const float* bl   = bias + (size_t)l * F;

        k_init <<<(NF + 255) / 256, 256>>>(aggp);
        k_uv   <<<R, F>>>(Wl, ql, kl);
        k_gemm <<<dim3((N_NODES + 127) / 128, R), 256>>>(h, Wl);
        k_aqak <<<(N_NODES * 32 + 255) / 256, 256>>>(h);
        k_logit<<<(N_EDGES + 255) / 256, 256>>>(ei, et);
        k_exp  <<<(N_EDGES + 255) / 256, 256>>>(ei);
        k_agg  <<<(N_EDGES * 32 + 255) / 256, 256>>>(ei, et, aggp);
        k_fin  <<<(NF + 255) / 256, 256>>>(aggp, bl, aggp);
    }
}

// round 7
// speedup vs baseline: 1.8396x; 1.0600x over previous
#include <cuda_runtime.h>
#include <math.h>

#define N_NODES 50000
#define N_EDGES 500000
#define F 128
#define R 8

// ---------------- scratch (device globals; no allocations allowed) ----------
__device__ float g_xw[(size_t)R * N_NODES * F];   // 204.8 MB: per-relation projected feats
__device__ float g_h1[(size_t)N_NODES * F];       // layer-1 output / layer-2 input
__device__ float g_aq[R * N_NODES];
__device__ float g_ak[R * N_NODES];
__device__ float g_u[R * F];
__device__ float g_v[R * F];
// CSR by destination (built once; edge_index is layer-invariant)
__device__ int g_deg[N_NODES];
__device__ int g_pos[N_NODES];
__device__ int g_off[N_NODES + 1];
__device__ int g_eid[N_EDGES];

// ---------------- helpers ----------------
__device__ __forceinline__ float cvt_tf32(float x) {
    unsigned int o;
    asm("cvt.rna.tf32.f32 %0, %1;" : "=r"(o) : "f"(x));
    return __uint_as_float(o);
}

__device__ __forceinline__ void mma_tf32(float* c, const float* a, const float* b) {
    asm volatile(
        "mma.sync.aligned.m16n8k8.row.col.f32.tf32.tf32.f32 "
        "{%0,%1,%2,%3}, {%4,%5,%6,%7}, {%8,%9}, {%0,%1,%2,%3};"
        : "+f"(c[0]), "+f"(c[1]), "+f"(c[2]), "+f"(c[3])
        : "r"(__float_as_uint(a[0])), "r"(__float_as_uint(a[1])),
          "r"(__float_as_uint(a[2])), "r"(__float_as_uint(a[3])),
          "r"(__float_as_uint(b[0])), "r"(__float_as_uint(b[1])));
}

// ---------------- CSR build (once) ----------------
__global__ void k_csr0() {
    int i = blockIdx.x * blockDim.x + threadIdx.x;
    if (i < N_NODES) { g_deg[i] = 0; g_pos[i] = 0; }
}

__global__ void k_hist(const int* __restrict__ ei) {
    int e = blockIdx.x * blockDim.x + threadIdx.x;
    if (e < N_EDGES) atomicAdd(&g_deg[ei[N_EDGES + e]], 1);
}

// single-block exclusive scan over g_deg -> g_off
__global__ void __launch_bounds__(1024) k_scan() {
    __shared__ int s[1024];
    __shared__ int carry;
    int tid = threadIdx.x;
    if (tid == 0) carry = 0;
    __syncthreads();
    const int nchunk = (N_NODES + 1023) / 1024;
    for (int c = 0; c < nchunk; c++) {
        int i = c * 1024 + tid;
        int v = (i < N_NODES) ? g_deg[i] : 0;
        s[tid] = v;
        __syncthreads();
#pragma unroll
        for (int off = 1; off < 1024; off <<= 1) {
            int t = (tid >= off) ? s[tid - off] : 0;
            __syncthreads();
            s[tid] += t;
            __syncthreads();
        }
        if (i < N_NODES) g_off[i] = carry + s[tid] - v;
        int total = s[1023];
        __syncthreads();
        if (tid == 0) carry += total;
        __syncthreads();
    }
    if (tid == 0) g_off[N_NODES] = carry;
}

__global__ void k_scatter(const int* __restrict__ ei) {
    int e = blockIdx.x * blockDim.x + threadIdx.x;
    if (e >= N_EDGES) return;
    int d = ei[N_EDGES + e];
    int p = atomicAdd(&g_pos[d], 1);
    g_eid[g_off[d] + p] = e;
}

// ---------------- per-layer kernels ----------------

// u_r = W_r q, v_r = W_r k
__global__ void k_uv(const float* __restrict__ Wl, const float* __restrict__ q,
                     const float* __restrict__ kv) {
    __shared__ float qs[F], ks[F];
    int r = blockIdx.x, f = threadIdx.x;
    qs[f] = q[f]; ks[f] = kv[f];
    __syncthreads();
    const float* Wr = Wl + ((size_t)r * F + f) * F;
    float su = 0.f, sv = 0.f;
#pragma unroll 8
    for (int g = 0; g < F; g++) { float w = Wr[g]; su += w * qs[g]; sv += w * ks[g]; }
    g_u[r * F + f] = su;
    g_v[r * F + f] = sv;
}

// xw[r] = h @ W_r via tf32 mma.sync  (BM=128, BN=128, BK=32, 8 warps 4x2)
__global__ void __launch_bounds__(256) k_gemm(const float* __restrict__ h,
                                              const float* __restrict__ Wl) {
    __shared__ float Hs[128][36];
    __shared__ float Ws[32][136];
    const int r   = blockIdx.y;
    const int n0  = blockIdx.x * 128;
    const int tid = threadIdx.x;
    const int lane = tid & 31, wid = tid >> 5;
    const int warp_m = wid & 3;
    const int warp_n = wid >> 2;
    const float* Wr = Wl + (size_t)r * F * F;

    float c[2][8][4];
#pragma unroll
    for (int mt = 0; mt < 2; mt++)
#pragma unroll
        for (int nt = 0; nt < 8; nt++)
#pragma unroll
            for (int i = 0; i < 4; i++) c[mt][nt][i] = 0.f;

    for (int kt = 0; kt < F; kt += 32) {
#pragma unroll
        for (int i = 0; i < 4; i++) {
            int t = tid + i * 256;
            int row = t >> 3, q4 = t & 7;
            int gn = n0 + row;
            float4 v = make_float4(0.f, 0.f, 0.f, 0.f);
            if (gn < N_NODES)
                v = *(const float4*)(h + (size_t)gn * F + kt + q4 * 4);
            Hs[row][q4 * 4 + 0] = cvt_tf32(v.x); Hs[row][q4 * 4 + 1] = cvt_tf32(v.y);
            Hs[row][q4 * 4 + 2] = cvt_tf32(v.z); Hs[row][q4 * 4 + 3] = cvt_tf32(v.w);
        }
#pragma unroll
        for (int i = 0; i < 4; i++) {
            int t = tid + i * 256;
            int kk = t >> 5, q4 = t & 31;
            float4 v = *(const float4*)(Wr + (size_t)(kt + kk) * F + q4 * 4);
            Ws[kk][q4 * 4 + 0] = cvt_tf32(v.x); Ws[kk][q4 * 4 + 1] = cvt_tf32(v.y);
            Ws[kk][q4 * 4 + 2] = cvt_tf32(v.z); Ws[kk][q4 * 4 + 3] = cvt_tf32(v.w);
        }
        __syncthreads();

#pragma unroll
        for (int ks = 0; ks < 4; ks++) {
            const int k0 = ks * 8;
            float a[2][4];
#pragma unroll
            for (int mt = 0; mt < 2; mt++) {
                int row = warp_m * 32 + mt * 16 + (lane >> 2);
                int col = k0 + (lane & 3);
                a[mt][0] = Hs[row][col];
                a[mt][1] = Hs[row + 8][col];
                a[mt][2] = Hs[row][col + 4];
                a[mt][3] = Hs[row + 8][col + 4];
            }
            float b[8][2];
#pragma unroll
            for (int nt = 0; nt < 8; nt++) {
                int brow = k0 + (lane & 3);
                int bcol = warp_n * 64 + nt * 8 + (lane >> 2);
                b[nt][0] = Ws[brow][bcol];
                b[nt][1] = Ws[brow + 4][bcol];
            }
#pragma unroll
            for (int mt = 0; mt < 2; mt++)
#pragma unroll
                for (int nt = 0; nt < 8; nt++)
                    mma_tf32(c[mt][nt], a[mt], b[nt]);
        }
        __syncthreads();
    }

    float* out = g_xw + (size_t)r * N_NODES * F;
#pragma unroll
    for (int mt = 0; mt < 2; mt++) {
        int row0 = warp_m * 32 + mt * 16 + (lane >> 2);
#pragma unroll
        for (int half = 0; half < 2; half++) {
            int gn = n0 + row0 + half * 8;
            if (gn < N_NODES) {
#pragma unroll
                for (int nt = 0; nt < 8; nt++) {
                    int col = warp_n * 64 + nt * 8 + 2 * (lane & 3);
                    float2 val;
                    val.x = c[mt][nt][half * 2 + 0];
                    val.y = c[mt][nt][half * 2 + 1];
                    *(float2*)(out + (size_t)gn * F + col) = val;
                }
            }
        }
    }
}

// aq[r,n] = h_n . u_r ; ak[r,n] = h_n . v_r   (one warp per node)
__global__ void k_aqak(const float* __restrict__ h) {
    __shared__ float us[R * F], vs[R * F];
    int tid = threadIdx.x;
    for (int i = tid; i < R * F; i += blockDim.x) { us[i] = g_u[i]; vs[i] = g_v[i]; }
    __syncthreads();
    int gidx = blockIdx.x * blockDim.x + tid;
    int n = gidx >> 5, lane = gidx & 31;
    if (n >= N_NODES) return;
    float4 hv = ((const float4*)h)[(size_t)n * 32 + lane];
#pragma unroll
    for (int r = 0; r < R; r++) {
        const float* u = us + r * F + lane * 4;
        const float* v = vs + r * F + lane * 4;
        float s = hv.x * u[0] + hv.y * u[1] + hv.z * u[2] + hv.w * u[3];
        float t = hv.x * v[0] + hv.y * v[1] + hv.z * v[2] + hv.w * v[3];
#pragma unroll
        for (int o = 16; o; o >>= 1) {
            s += __shfl_xor_sync(0xffffffffu, s, o);
            t += __shfl_xor_sync(0xffffffffu, t, o);
        }
        if (lane == 0) { g_aq[r * N_NODES + n] = s; g_ak[r * N_NODES + n] = t; }
    }
}

// fused per-dst softmax + aggregation + bias + relu (warp per node, no atomics)
__global__ void __launch_bounds__(256) k_attn(const int* __restrict__ ei,
                                              const int* __restrict__ et,
                                              const float* __restrict__ bias,
                                              float* __restrict__ out) {
    int gidx = blockIdx.x * blockDim.x + threadIdx.x;
    int n = gidx >> 5, lane = gidx & 31;
    if (n >= N_NODES) return;
    const int start = g_off[n], end = g_off[n + 1];

    // pass 1: segment max (lane-parallel over edges)
    float m = -INFINITY;
    for (int i = start + lane; i < end; i += 32) {
        int e = g_eid[i];
        int s = ei[e], r = et[e];
        float lg = g_aq[r * N_NODES + n] + g_ak[r * N_NODES + s];
        lg = lg > 0.f ? lg : 0.2f * lg;
        m = fmaxf(m, lg);
    }
#pragma unroll
    for (int o = 16; o; o >>= 1) m = fmaxf(m, __shfl_xor_sync(0xffffffffu, m, o));

    // pass 2: weighted feature accumulate (warp-cooperative per edge, x2 unroll)
    float4 acc = make_float4(0.f, 0.f, 0.f, 0.f);
    float den = 0.f;
    const float aqn_base = 0.f; (void)aqn_base;
    int i = start;
    for (; i + 1 < end; i += 2) {
        int e0 = g_eid[i], e1 = g_eid[i + 1];
        int s0 = ei[e0], r0 = et[e0];
        int s1 = ei[e1], r1 = et[e1];
        float lg0 = g_aq[r0 * N_NODES + n] + g_ak[r0 * N_NODES + s0];
        float lg1 = g_aq[r1 * N_NODES + n] + g_ak[r1 * N_NODES + s1];
        lg0 = lg0 > 0.f ? lg0 : 0.2f * lg0;
        lg1 = lg1 > 0.f ? lg1 : 0.2f * lg1;
        float w0 = expf(lg0 - m), w1 = expf(lg1 - m);
        const float4 x0 = ((const float4*)(g_xw + ((size_t)r0 * N_NODES + s0) * F))[lane];
        const float4 x1 = ((const float4*)(g_xw + ((size_t)r1 * N_NODES + s1) * F))[lane];
        acc.x += w0 * x0.x + w1 * x1.x;
        acc.y += w0 * x0.y + w1 * x1.y;
        acc.z += w0 * x0.z + w1 * x1.z;
        acc.w += w0 * x0.w + w1 * x1.w;
        den += w0 + w1;
    }
    if (i < end) {
        int e0 = g_eid[i];
        int s0 = ei[e0], r0 = et[e0];
        float lg0 = g_aq[r0 * N_NODES + n] + g_ak[r0 * N_NODES + s0];
        lg0 = lg0 > 0.f ? lg0 : 0.2f * lg0;
        float w0 = expf(lg0 - m);
        const float4 x0 = ((const float4*)(g_xw + ((size_t)r0 * N_NODES + s0) * F))[lane];
        acc.x += w0 * x0.x; acc.y += w0 * x0.y;
        acc.z += w0 * x0.z; acc.w += w0 * x0.w;
        den += w0;
    }

    float inv = 1.0f / (den + 1e-16f);
    float4 bs = ((const float4*)bias)[lane];
    float4 o4;
    o4.x = fmaxf(acc.x * inv + bs.x, 0.f);
    o4.y = fmaxf(acc.y * inv + bs.y, 0.f);
    o4.z = fmaxf(acc.z * inv + bs.z, 0.f);
    o4.w = fmaxf(acc.w * inv + bs.w, 0.f);
    ((float4*)(out + (size_t)n * F))[lane] = o4;
}

// ---------------- launch ----------------
extern "C" void kernel_launch(void* const* d_in, const int* in_sizes, int n_in,
                              void* d_out, int out_size) {
    const float* x    = (const float*)d_in[0];
    const float* W    = (const float*)d_in[1];
    const float* attq = (const float*)d_in[2];
    const float* attk = (const float*)d_in[3];
    const float* bias = (const float*)d_in[4];
    const int*   ei   = (const int*)d_in[5];
    const int*   et   = (const int*)d_in[6];
    float* out = (float*)d_out;

    float* h1_ptr = nullptr;
    cudaGetSymbolAddress((void**)&h1_ptr, g_h1);

    // CSR by dst: layer-invariant, build once
    k_csr0   <<<(N_NODES + 255) / 256, 256>>>();
    k_hist   <<<(N_EDGES + 255) / 256, 256>>>(ei);
    k_scan   <<<1, 1024>>>();
    k_scatter<<<(N_EDGES + 255) / 256, 256>>>(ei);

    for (int l = 0; l < 2; l++) {
        const float* h    = (l == 0) ? x : h1_ptr;
        float*       op   = (l == 0) ? h1_ptr : out;
        const float* Wl   = W + (size_t)l * R * F * F;
        const float* ql   = attq + (size_t)l * F;
        const float* kl   = attk + (size_t)l * F;
        const float* bl   = bias + (size_t)l * F;

        k_uv  <<<R, F>>>(Wl, ql, kl);
        k_gemm<<<dim3((N_NODES + 127) / 128, R), 256>>>(h, Wl);
        k_aqak<<<(N_NODES * 32 + 255) / 256, 256>>>(h);
        k_attn<<<(N_NODES * 32 + 255) / 256, 256>>>(ei, et, bl, op);
    }
}

// round 11
// speedup vs baseline: 2.4415x; 1.3272x over previous
#include <cuda_runtime.h>
#include <cuda_fp16.h>
#include <math.h>

#define N_NODES 50000
#define N_EDGES 500000
#define F 128
#define R 8

// ---------------- scratch (device globals; no allocations allowed) ----------
__device__ __half g_xwh[(size_t)R * N_NODES * F];  // 102.4 MB: fp16 projected feats (L2-resident)
__device__ float g_h1[(size_t)N_NODES * F];        // layer-1 output / layer-2 input
__device__ float g_aq[R * N_NODES];
__device__ float g_ak[R * N_NODES];
// CSR by destination (built once; edge_index is layer-invariant)
__device__ int g_deg[N_NODES];
__device__ int g_pos[N_NODES];
__device__ int g_off[N_NODES + 1];
__device__ int g_eid[N_EDGES];

// ---------------- helpers ----------------
__device__ __forceinline__ float cvt_tf32(float x) {
    unsigned int o;
    asm("cvt.rna.tf32.f32 %0, %1;" : "=r"(o) : "f"(x));
    return __uint_as_float(o);
}

__device__ __forceinline__ void mma_tf32(float* c, const float* a, const float* b) {
    asm volatile(
        "mma.sync.aligned.m16n8k8.row.col.f32.tf32.tf32.f32 "
        "{%0,%1,%2,%3}, {%4,%5,%6,%7}, {%8,%9}, {%0,%1,%2,%3};"
        : "+f"(c[0]), "+f"(c[1]), "+f"(c[2]), "+f"(c[3])
        : "r"(__float_as_uint(a[0])), "r"(__float_as_uint(a[1])),
          "r"(__float_as_uint(a[2])), "r"(__float_as_uint(a[3])),
          "r"(__float_as_uint(b[0])), "r"(__float_as_uint(b[1])));
}

// ---------------- CSR build (once) ----------------
__global__ void k_csr0() {
    int i = blockIdx.x * blockDim.x + threadIdx.x;
    if (i < N_NODES) { g_deg[i] = 0; g_pos[i] = 0; }
}

__global__ void k_hist(const int* __restrict__ ei) {
    int e = blockIdx.x * blockDim.x + threadIdx.x;
    if (e < N_EDGES) atomicAdd(&g_deg[ei[N_EDGES + e]], 1);
}

// single-block exclusive scan over g_deg -> g_off (warp-shuffle based)
__global__ void __launch_bounds__(1024) k_scan() {
    __shared__ int wsum[32];
    __shared__ int carry_s;
    int tid = threadIdx.x, lane = tid & 31, wid = tid >> 5;
    if (tid == 0) carry_s = 0;
    __syncthreads();
    const int nchunk = (N_NODES + 1023) / 1024;
    for (int c = 0; c < nchunk; c++) {
        int i = c * 1024 + tid;
        int v = (i < N_NODES) ? g_deg[i] : 0;
        int x = v;
#pragma unroll
        for (int o = 1; o < 32; o <<= 1) {
            int t = __shfl_up_sync(0xffffffffu, x, o);
            if (lane >= o) x += t;
        }
        if (lane == 31) wsum[wid] = x;
        __syncthreads();
        if (wid == 0) {
            int s = wsum[lane];
#pragma unroll
            for (int o = 1; o < 32; o <<= 1) {
                int t = __shfl_up_sync(0xffffffffu, s, o);
                if (lane >= o) s += t;
            }
            wsum[lane] = s;
        }
        __syncthreads();
        int base = carry_s + (wid ? wsum[wid - 1] : 0);
        if (i < N_NODES) g_off[i] = base + x - v;
        __syncthreads();
        if (tid == 0) carry_s += wsum[31];
        __syncthreads();
    }
    if (tid == 0) g_off[N_NODES] = carry_s;
}

__global__ void k_scatter(const int* __restrict__ ei) {
    int e = blockIdx.x * blockDim.x + threadIdx.x;
    if (e >= N_EDGES) return;
    int d = ei[N_EDGES + e];
    int p = atomicAdd(&g_pos[d], 1);
    g_eid[g_off[d] + p] = e;
}

// ---------------- per-layer kernels ----------------

// xw[r] = h @ W_r via tf32 mma.sync; fp16 output; fused aq/ak epilogue.
__global__ void __launch_bounds__(256) k_gemm(const float* __restrict__ h,
                                              const float* __restrict__ Wl,
                                              const float* __restrict__ q,
                                              const float* __restrict__ kv) {
    __shared__ float Hs[128][36];
    __shared__ float Ws[32][136];
    __shared__ float qs[F], ks[F];
    __shared__ float aq_s[2][128], ak_s[2][128];
    const int r   = blockIdx.y;
    const int n0  = blockIdx.x * 128;
    const int tid = threadIdx.x;
    const int lane = tid & 31, wid = tid >> 5;
    const int warp_m = wid & 3;
    const int warp_n = wid >> 2;
    const float* Wr = Wl + (size_t)r * F * F;

    if (tid < F) { qs[tid] = q[tid]; ks[tid] = kv[tid]; }

    float c[2][8][4];
#pragma unroll
    for (int mt = 0; mt < 2; mt++)
#pragma unroll
        for (int nt = 0; nt < 8; nt++)
#pragma unroll
            for (int i = 0; i < 4; i++) c[mt][nt][i] = 0.f;

    for (int kt = 0; kt < F; kt += 32) {
#pragma unroll
        for (int i = 0; i < 4; i++) {
            int t = tid + i * 256;
            int row = t >> 3, q4 = t & 7;
            int gn = n0 + row;
            float4 v = make_float4(0.f, 0.f, 0.f, 0.f);
            if (gn < N_NODES)
                v = *(const float4*)(h + (size_t)gn * F + kt + q4 * 4);
            Hs[row][q4 * 4 + 0] = cvt_tf32(v.x); Hs[row][q4 * 4 + 1] = cvt_tf32(v.y);
            Hs[row][q4 * 4 + 2] = cvt_tf32(v.z); Hs[row][q4 * 4 + 3] = cvt_tf32(v.w);
        }
#pragma unroll
        for (int i = 0; i < 4; i++) {
            int t = tid + i * 256;
            int kk = t >> 5, q4 = t & 31;
            float4 v = *(const float4*)(Wr + (size_t)(kt + kk) * F + q4 * 4);
            Ws[kk][q4 * 4 + 0] = cvt_tf32(v.x); Ws[kk][q4 * 4 + 1] = cvt_tf32(v.y);
            Ws[kk][q4 * 4 + 2] = cvt_tf32(v.z); Ws[kk][q4 * 4 + 3] = cvt_tf32(v.w);
        }
        __syncthreads();

#pragma unroll
        for (int ks8 = 0; ks8 < 4; ks8++) {
            const int k0 = ks8 * 8;
            float a[2][4];
#pragma unroll
            for (int mt = 0; mt < 2; mt++) {
                int row = warp_m * 32 + mt * 16 + (lane >> 2);
                int col = k0 + (lane & 3);
                a[mt][0] = Hs[row][col];
                a[mt][1] = Hs[row + 8][col];
                a[mt][2] = Hs[row][col + 4];
                a[mt][3] = Hs[row + 8][col + 4];
            }
            float b[8][2];
#pragma unroll
            for (int nt = 0; nt < 8; nt++) {
                int brow = k0 + (lane & 3);
                int bcol = warp_n * 64 + nt * 8 + (lane >> 2);
                b[nt][0] = Ws[brow][bcol];
                b[nt][1] = Ws[brow + 4][bcol];
            }
#pragma unroll
            for (int mt = 0; mt < 2; mt++)
#pragma unroll
                for (int nt = 0; nt < 8; nt++)
                    mma_tf32(c[mt][nt], a[mt], b[nt]);
        }
        __syncthreads();
    }

    // ---- epilogue: fp16 store + per-row q/k dots ----
    __half* out = g_xwh + (size_t)r * N_NODES * F;
    float paq[2][2] = {{0.f, 0.f}, {0.f, 0.f}};
    float pak[2][2] = {{0.f, 0.f}, {0.f, 0.f}};
#pragma unroll
    for (int mt = 0; mt < 2; mt++) {
        int row0 = warp_m * 32 + mt * 16 + (lane >> 2);
#pragma unroll
        for (int half_ = 0; half_ < 2; half_++) {
            int gn = n0 + row0 + half_ * 8;
            bool ok = (gn < N_NODES);
#pragma unroll
            for (int nt = 0; nt < 8; nt++) {
                int col = warp_n * 64 + nt * 8 + 2 * (lane & 3);
                float v0 = c[mt][nt][half_ * 2 + 0];
                float v1 = c[mt][nt][half_ * 2 + 1];
                paq[mt][half_] += v0 * qs[col] + v1 * qs[col + 1];
                pak[mt][half_] += v0 * ks[col] + v1 * ks[col + 1];
                if (ok)
                    *(__half2*)(out + (size_t)gn * F + col) = __floats2half2_rn(v0, v1);
            }
        }
    }
    // reduce quad (lane&3) then combine the two warp_n halves via smem
#pragma unroll
    for (int mt = 0; mt < 2; mt++)
#pragma unroll
        for (int half_ = 0; half_ < 2; half_++) {
            float a_ = paq[mt][half_], k_ = pak[mt][half_];
            a_ += __shfl_xor_sync(0xffffffffu, a_, 1);
            a_ += __shfl_xor_sync(0xffffffffu, a_, 2);
            k_ += __shfl_xor_sync(0xffffffffu, k_, 1);
            k_ += __shfl_xor_sync(0xffffffffu, k_, 2);
            if ((lane & 3) == 0) {
                int row = warp_m * 32 + mt * 16 + half_ * 8 + (lane >> 2);
                aq_s[warp_n][row] = a_;
                ak_s[warp_n][row] = k_;
            }
        }
    __syncthreads();
    if (tid < 128) {
        int gn = n0 + tid;
        if (gn < N_NODES) {
            g_aq[r * N_NODES + gn] = aq_s[0][tid] + aq_s[1][tid];
            g_ak[r * N_NODES + gn] = ak_s[0][tid] + ak_s[1][tid];
        }
    }
}

// fused per-dst softmax + aggregation + bias + relu (warp per node, no atomics)
__global__ void __launch_bounds__(256) k_attn(const int* __restrict__ ei,
                                              const int* __restrict__ et,
                                              const float* __restrict__ bias,
                                              float* __restrict__ out) {
    int gidx = blockIdx.x * blockDim.x + threadIdx.x;
    int n = gidx >> 5, lane = gidx & 31;
    if (n >= N_NODES) return;
    const int start = g_off[n], end = g_off[n + 1];

    // pass 1: segment max (lane-parallel over edges)
    float m = -INFINITY;
    for (int i = start + lane; i < end; i += 32) {
        int e = g_eid[i];
        int s = ei[e], r = et[e];
        float lg = g_aq[r * N_NODES + n] + g_ak[r * N_NODES + s];
        lg = lg > 0.f ? lg : 0.2f * lg;
        m = fmaxf(m, lg);
    }
#pragma unroll
    for (int o = 16; o; o >>= 1) m = fmaxf(m, __shfl_xor_sync(0xffffffffu, m, o));

    // pass 2: weighted feature accumulate (warp-cooperative per edge, x2 unroll)
    float4 acc = make_float4(0.f, 0.f, 0.f, 0.f);
    float den = 0.f;
    int i = start;
    for (; i + 1 < end; i += 2) {
        int e0 = g_eid[i], e1 = g_eid[i + 1];
        int s0 = ei[e0], r0 = et[e0];
        int s1 = ei[e1], r1 = et[e1];
        float lg0 = g_aq[r0 * N_NODES + n] + g_ak[r0 * N_NODES + s0];
        float lg1 = g_aq[r1 * N_NODES + n] + g_ak[r1 * N_NODES + s1];
        lg0 = lg0 > 0.f ? lg0 : 0.2f * lg0;
        lg1 = lg1 > 0.f ? lg1 : 0.2f * lg1;
        float w0 = expf(lg0 - m), w1 = expf(lg1 - m);
        const uint2* x0p = (const uint2*)(g_xwh + ((size_t)r0 * N_NODES + s0) * F);
        const uint2* x1p = (const uint2*)(g_xwh + ((size_t)r1 * N_NODES + s1) * F);
        uint2 p0 = x0p[lane], p1 = x1p[lane];
        float2 a01 = __half22float2(*(__half2*)&p0.x);
        float2 a23 = __half22float2(*(__half2*)&p0.y);
        float2 b01 = __half22float2(*(__half2*)&p1.x);
        float2 b23 = __half22float2(*(__half2*)&p1.y);
        acc.x += w0 * a01.x + w1 * b01.x;
        acc.y += w0 * a01.y + w1 * b01.y;
        acc.z += w0 * a23.x + w1 * b23.x;
        acc.w += w0 * a23.y + w1 * b23.y;
        den += w0 + w1;
    }
    if (i < end) {
        int e0 = g_eid[i];
        int s0 = ei[e0], r0 = et[e0];
        float lg0 = g_aq[r0 * N_NODES + n] + g_ak[r0 * N_NODES + s0];
        lg0 = lg0 > 0.f ? lg0 : 0.2f * lg0;
        float w0 = expf(lg0 - m);
        const uint2* x0p = (const uint2*)(g_xwh + ((size_t)r0 * N_NODES + s0) * F);
        uint2 p0 = x0p[lane];
        float2 a01 = __half22float2(*(__half2*)&p0.x);
        float2 a23 = __half22float2(*(__half2*)&p0.y);
        acc.x += w0 * a01.x; acc.y += w0 * a01.y;
        acc.z += w0 * a23.x; acc.w += w0 * a23.y;
        den += w0;
    }

    float inv = 1.0f / (den + 1e-16f);
    float4 bs = ((const float4*)bias)[lane];
    float4 o4;
    o4.x = fmaxf(acc.x * inv + bs.x, 0.f);
    o4.y = fmaxf(acc.y * inv + bs.y, 0.f);
    o4.z = fmaxf(acc.z * inv + bs.z, 0.f);
    o4.w = fmaxf(acc.w * inv + bs.w, 0.f);
    ((float4*)(out + (size_t)n * F))[lane] = o4;
}

// ---------------- launch ----------------
extern "C" void kernel_launch(void* const* d_in, const int* in_sizes, int n_in,
                              void* d_out, int out_size) {
    const float* x    = (const float*)d_in[0];
    const float* W    = (const float*)d_in[1];
    const float* attq = (const float*)d_in[2];
    const float* attk = (const float*)d_in[3];
    const float* bias = (const float*)d_in[4];
    const int*   ei   = (const int*)d_in[5];
    const int*   et   = (const int*)d_in[6];
    float* out = (float*)d_out;

    float* h1_ptr = nullptr;
    cudaGetSymbolAddress((void**)&h1_ptr, g_h1);

    // CSR by dst: layer-invariant, build once per call
    k_csr0   <<<(N_NODES + 255) / 256, 256>>>();
    k_hist   <<<(N_EDGES + 255) / 256, 256>>>(ei);
    k_scan   <<<1, 1024>>>();
    k_scatter<<<(N_EDGES + 255) / 256, 256>>>(ei);

    for (int l = 0; l < 2; l++) {
        const float* h    = (l == 0) ? x : h1_ptr;
        float*       op   = (l == 0) ? h1_ptr : out;
        const float* Wl   = W + (size_t)l * R * F * F;
        const float* ql   = attq + (size_t)l * F;
        const float* kl   = attk + (size_t)l * F;
        const float* bl   = bias + (size_t)l * F;

        k_gemm<<<dim3((N_NODES + 127) / 128, R), 256>>>(h, Wl, ql, kl);
        k_attn<<<(N_NODES * 32 + 255) / 256, 256>>>(ei, et, bl, op);
    }
}

// round 17
// speedup vs baseline: 3.1947x; 1.3085x over previous
#include <cuda_runtime.h>
#include <cuda_fp16.h>
#include <cstdint>
#include <math.h>

#define N_NODES 50000
#define N_EDGES 500000
#define F 128
#define R 8

// ---------------- scratch (device globals; no allocations allowed) ----------
__device__ __half g_xwh[(size_t)R * N_NODES * F];  // 102.4 MB fp16 projected feats (L2-resident)
__device__ __half g_hh[(size_t)N_NODES * F];       // fp16 node features (layer input)
__device__ float g_aq[R * N_NODES];
__device__ float g_ak[R * N_NODES];
// CSR by destination (built once; edge_index is layer-invariant)
__device__ int g_deg[N_NODES];
__device__ int g_pos[N_NODES];
__device__ int g_off[N_NODES + 1];
__device__ int g_esr[N_EDGES];    // packed (rel<<16) | src per CSR slot

// ---------------- helpers ----------------
__device__ __forceinline__ void ldm_x4(unsigned& r0, unsigned& r1, unsigned& r2, unsigned& r3,
                                       const void* p) {
    unsigned int a = (unsigned int)__cvta_generic_to_shared(p);
    asm volatile("ldmatrix.sync.aligned.m8n8.x4.shared.b16 {%0,%1,%2,%3}, [%4];"
                 : "=r"(r0), "=r"(r1), "=r"(r2), "=r"(r3) : "r"(a));
}

__device__ __forceinline__ void ldm_x4_t(unsigned& r0, unsigned& r1, unsigned& r2, unsigned& r3,
                                         const void* p) {
    unsigned int a = (unsigned int)__cvta_generic_to_shared(p);
    asm volatile("ldmatrix.sync.aligned.m8n8.x4.trans.shared.b16 {%0,%1,%2,%3}, [%4];"
                 : "=r"(r0), "=r"(r1), "=r"(r2), "=r"(r3) : "r"(a));
}

__device__ __forceinline__ void mma_f16(float* c, const unsigned* a, const unsigned* b) {
    asm volatile(
        "mma.sync.aligned.m16n8k16.row.col.f32.f16.f16.f32 "
        "{%0,%1,%2,%3}, {%4,%5,%6,%7}, {%8,%9}, {%0,%1,%2,%3};"
        : "+f"(c[0]), "+f"(c[1]), "+f"(c[2]), "+f"(c[3])
        : "r"(a[0]), "r"(a[1]), "r"(a[2]), "r"(a[3]), "r"(b[0]), "r"(b[1]));
}

// ---------------- CSR build (once) ----------------
__global__ void k_csr0() {
    int i = blockIdx.x * blockDim.x + threadIdx.x;
    if (i < N_NODES) { g_deg[i] = 0; g_pos[i] = 0; }
}

__global__ void k_hist(const int* __restrict__ ei) {
    int e = blockIdx.x * blockDim.x + threadIdx.x;
    if (e < N_EDGES) atomicAdd(&g_deg[ei[N_EDGES + e]], 1);
}

// single-block exclusive scan over g_deg -> g_off (warp-shuffle based)
__global__ void __launch_bounds__(1024) k_scan() {
    __shared__ int wsum[32];
    __shared__ int carry_s;
    int tid = threadIdx.x, lane = tid & 31, wid = tid >> 5;
    if (tid == 0) carry_s = 0;
    __syncthreads();
    const int nchunk = (N_NODES + 1023) / 1024;
    for (int c = 0; c < nchunk; c++) {
        int i = c * 1024 + tid;
        int v = (i < N_NODES) ? g_deg[i] : 0;
        int x = v;
#pragma unroll
        for (int o = 1; o < 32; o <<= 1) {
            int t = __shfl_up_sync(0xffffffffu, x, o);
            if (lane >= o) x += t;
        }
        if (lane == 31) wsum[wid] = x;
        __syncthreads();
        if (wid == 0) {
            int s = wsum[lane];
#pragma unroll
            for (int o = 1; o < 32; o <<= 1) {
                int t = __shfl_up_sync(0xffffffffu, s, o);
                if (lane >= o) s += t;
            }
            wsum[lane] = s;
        }
        __syncthreads();
        int base = carry_s + (wid ? wsum[wid - 1] : 0);
        if (i < N_NODES) g_off[i] = base + x - v;
        __syncthreads();
        if (tid == 0) carry_s += wsum[31];
        __syncthreads();
    }
    if (tid == 0) g_off[N_NODES] = carry_s;
}

__global__ void k_scatter(const int* __restrict__ ei, const int* __restrict__ et) {
    int e = blockIdx.x * blockDim.x + threadIdx.x;
    if (e >= N_EDGES) return;
    int s = ei[e], d = ei[N_EDGES + e], r = et[e];
    int p = atomicAdd(&g_pos[d], 1);
    g_esr[g_off[d] + p] = (r << 16) | s;
}

// x (fp32) -> g_hh (fp16)
__global__ void k_cvt(const float* __restrict__ x) {
    int i = blockIdx.x * blockDim.x + threadIdx.x;   // one float4 per thread
    if (i >= N_NODES * F / 4) return;
    float4 v = ((const float4*)x)[i];
    __half2 h0 = __floats2half2_rn(v.x, v.y);
    __half2 h1 = __floats2half2_rn(v.z, v.w);
    uint2 p;
    p.x = *(unsigned*)&h0; p.y = *(unsigned*)&h1;
    ((uint2*)g_hh)[i] = p;
}

// ---------------- GEMM: xw[r] = h @ W_r  (fp16 mma m16n8k16, fused aq/ak) --
__global__ void __launch_bounds__(256) k_gemm(const float* __restrict__ Wl,
                                              const float* __restrict__ q,
                                              const float* __restrict__ kv) {
    __shared__ __half Hs[128][40];   // stride 20 words: conflict-free ldmatrix
    __shared__ __half Ws[32][136];   // stride 68 words (== 4 mod 32): conflict-free
    __shared__ float qs[F], ks[F];
    __shared__ float aq_s[2][128], ak_s[2][128];
    const int r   = blockIdx.y;
    const int n0  = blockIdx.x * 128;
    const int tid = threadIdx.x;
    const int lane = tid & 31, wid = tid >> 5;
    const int warp_m = wid & 3;      // 4 warps over M (32 rows)
    const int warp_n = wid >> 2;     // 2 warps over N (64 cols)
    const float* Wr = Wl + (size_t)r * F * F;

    if (tid < F) { qs[tid] = q[tid]; ks[tid] = kv[tid]; }

    float c[2][8][4];
#pragma unroll
    for (int mt = 0; mt < 2; mt++)
#pragma unroll
        for (int nt = 0; nt < 8; nt++)
#pragma unroll
            for (int i = 0; i < 4; i++) c[mt][nt][i] = 0.f;

    for (int kt = 0; kt < F; kt += 32) {
        // H tile: 128 rows x 32 halves (from fp16 g_hh, uint4 = 8 halves)
#pragma unroll
        for (int i = 0; i < 2; i++) {
            int idx = tid + i * 256;           // 0..511
            int row = idx >> 2, qq = idx & 3;
            int gn = n0 + row;
            uint4 v = make_uint4(0u, 0u, 0u, 0u);
            if (gn < N_NODES)
                v = *(const uint4*)(g_hh + (size_t)gn * F + kt + qq * 8);
            *(uint4*)&Hs[row][qq * 8] = v;
        }
        // W tile: 32 k-rows x 128 n (fp32 -> fp16)
#pragma unroll
        for (int i = 0; i < 4; i++) {
            int t = tid + i * 256;
            int kk = t >> 5, q4 = t & 31;
            float4 v = *(const float4*)(Wr + (size_t)(kt + kk) * F + q4 * 4);
            __half2 h0 = __floats2half2_rn(v.x, v.y);
            __half2 h1 = __floats2half2_rn(v.z, v.w);
            uint2 p; p.x = *(unsigned*)&h0; p.y = *(unsigned*)&h1;
            *(uint2*)&Ws[kk][q4 * 4] = p;
        }
        __syncthreads();

#pragma unroll
        for (int ks16 = 0; ks16 < 2; ks16++) {
            const int k0 = ks16 * 16;
            unsigned a[2][4];
#pragma unroll
            for (int mt = 0; mt < 2; mt++) {
                int row = warp_m * 32 + mt * 16 + (lane & 15);
                int col = k0 + (lane >> 4) * 8;
                ldm_x4(a[mt][0], a[mt][1], a[mt][2], a[mt][3], &Hs[row][col]);
            }
            unsigned b[4][4];
#pragma unroll
            for (int ntp = 0; ntp < 4; ntp++) {
                int krow = k0 + (lane & 7) + ((lane >> 3) & 1) * 8;
                int ncol = warp_n * 64 + ntp * 16 + (lane >> 4) * 8;
                ldm_x4_t(b[ntp][0], b[ntp][1], b[ntp][2], b[ntp][3], &Ws[krow][ncol]);
            }
#pragma unroll
            for (int mt = 0; mt < 2; mt++)
#pragma unroll
                for (int ntp = 0; ntp < 4; ntp++) {
                    mma_f16(c[mt][ntp * 2 + 0], a[mt], &b[ntp][0]);
                    mma_f16(c[mt][ntp * 2 + 1], a[mt], &b[ntp][2]);
                }
        }
        __syncthreads();
    }

    // ---- epilogue: fp16 store + fused per-row q/k dots ----
    __half* out = g_xwh + (size_t)r * N_NODES * F;
    float paq[2][2] = {{0.f, 0.f}, {0.f, 0.f}};
    float pak[2][2] = {{0.f, 0.f}, {0.f, 0.f}};
#pragma unroll
    for (int mt = 0; mt < 2; mt++) {
        int row0 = warp_m * 32 + mt * 16 + (lane >> 2);
#pragma unroll
        for (int half_ = 0; half_ < 2; half_++) {
            int gn = n0 + row0 + half_ * 8;
            bool ok = (gn < N_NODES);
#pragma unroll
            for (int nt = 0; nt < 8; nt++) {
                int col = warp_n * 64 + nt * 8 + 2 * (lane & 3);
                float v0 = c[mt][nt][half_ * 2 + 0];
                float v1 = c[mt][nt][half_ * 2 + 1];
                paq[mt][half_] += v0 * qs[col] + v1 * qs[col + 1];
                pak[mt][half_] += v0 * ks[col] + v1 * ks[col + 1];
                if (ok)
                    *(__half2*)(out + (size_t)gn * F + col) = __floats2half2_rn(v0, v1);
            }
        }
    }
#pragma unroll
    for (int mt = 0; mt < 2; mt++)
#pragma unroll
        for (int half_ = 0; half_ < 2; half_++) {
            float a_ = paq[mt][half_], k_ = pak[mt][half_];
            a_ += __shfl_xor_sync(0xffffffffu, a_, 1);
            a_ += __shfl_xor_sync(0xffffffffu, a_, 2);
            k_ += __shfl_xor_sync(0xffffffffu, k_, 1);
            k_ += __shfl_xor_sync(0xffffffffu, k_, 2);
            if ((lane & 3) == 0) {
                int row = warp_m * 32 + mt * 16 + half_ * 8 + (lane >> 2);
                aq_s[warp_n][row] = a_;
                ak_s[warp_n][row] = k_;
            }
        }
    __syncthreads();
    if (tid < 128) {
        int gn = n0 + tid;
        if (gn < N_NODES) {
            g_aq[r * N_NODES + gn] = aq_s[0][tid] + aq_s[1][tid];
            g_ak[r * N_NODES + gn] = ak_s[0][tid] + ak_s[1][tid];
        }
    }
}

// fused per-dst softmax + aggregation + bias + relu (warp per node, no atomics)
__global__ void __launch_bounds__(256) k_attn(const float* __restrict__ bias,
                                              float* __restrict__ outf,
                                              int write_half) {
    const unsigned FULL = 0xffffffffu;
    int gidx = blockIdx.x * blockDim.x + threadIdx.x;
    int n = gidx >> 5, lane = gidx & 31;
    if (n >= N_NODES) return;
    const int start = g_off[n], end = g_off[n + 1];
    const int deg = end - start;
    const int nch = (deg + 31) >> 5;

    // preload aq[r,n] for all 8 relations into lanes 0..7
    float aq_pre = (lane < R) ? g_aq[lane * N_NODES + n] : 0.f;

    float4 acc = make_float4(0.f, 0.f, 0.f, 0.f);
    float den = 0.f;

    if (nch <= 4) {
        float llg[4]; int lsr[4];
        float m = -INFINITY;
#pragma unroll
        for (int csel = 0; csel < 4; csel++) {
            if (csel < nch) {
                int idx = start + csel * 32 + lane;
                bool ok = idx < end;
                int esr = ok ? g_esr[idx] : 0;
                int s = esr & 0xffff, r = esr >> 16;
                float aqv = __shfl_sync(FULL, aq_pre, r);
                float akv = ok ? g_ak[r * N_NODES + s] : 0.f;
                float lg = aqv + akv;
                lg = lg > 0.f ? lg : 0.2f * lg;
                lg = ok ? lg : -INFINITY;
                llg[csel] = lg; lsr[csel] = esr;
                m = fmaxf(m, lg);
            }
        }
#pragma unroll
        for (int o = 16; o; o >>= 1) m = fmaxf(m, __shfl_xor_sync(FULL, m, o));

        float wl[4];
#pragma unroll
        for (int csel = 0; csel < 4; csel++) {
            if (csel < nch) {
                float w = (llg[csel] == -INFINITY) ? 0.f : expf(llg[csel] - m);
                wl[csel] = w;
                den += w;
            }
        }
#pragma unroll
        for (int o = 16; o; o >>= 1) den += __shfl_xor_sync(FULL, den, o);

        for (int csel = 0; csel < nch; csel++) {
            int base = start + csel * 32;
            int cnt = min(32, end - base);
            float wlc = wl[csel]; int src = lsr[csel];
            int j = 0;
            for (; j + 1 < cnt; j += 2) {
                float w0 = __shfl_sync(FULL, wlc, j);
                float w1 = __shfl_sync(FULL, wlc, j + 1);
                int e0 = __shfl_sync(FULL, src, j);
                int e1 = __shfl_sync(FULL, src, j + 1);
                int s0 = e0 & 0xffff, r0 = e0 >> 16;
                int s1 = e1 & 0xffff, r1 = e1 >> 16;
                uint2 p0 = ((const uint2*)(g_xwh + ((size_t)r0 * N_NODES + s0) * F))[lane];
                uint2 p1 = ((const uint2*)(g_xwh + ((size_t)r1 * N_NODES + s1) * F))[lane];
                float2 a01 = __half22float2(*(__half2*)&p0.x);
                float2 a23 = __half22float2(*(__half2*)&p0.y);
                float2 b01 = __half22float2(*(__half2*)&p1.x);
                float2 b23 = __half22float2(*(__half2*)&p1.y);
                acc.x += w0 * a01.x + w1 * b01.x;
                acc.y += w0 * a01.y + w1 * b01.y;
                acc.z += w0 * a23.x + w1 * b23.x;
                acc.w += w0 * a23.y + w1 * b23.y;
            }
            if (j < cnt) {
                float w0 = __shfl_sync(FULL, wlc, j);
                int e0 = __shfl_sync(FULL, src, j);
                int s0 = e0 & 0xffff, r0 = e0 >> 16;
                uint2 p0 = ((const uint2*)(g_xwh + ((size_t)r0 * N_NODES + s0) * F))[lane];
                float2 a01 = __half22float2(*(__half2*)&p0.x);
                float2 a23 = __half22float2(*(__half2*)&p0.y);
                acc.x += w0 * a01.x; acc.y += w0 * a01.y;
                acc.z += w0 * a23.x; acc.w += w0 * a23.y;
            }
        }
    } else {
        // fallback for very high degree (recompute logits per edge)
        float m = -INFINITY;
        for (int cc = 0; cc < nch; cc++) {
            int idx = start + cc * 32 + lane;
            bool ok = idx < end;
            int esr = ok ? g_esr[idx] : 0;
            int s = esr & 0xffff, r = esr >> 16;
            float aqv = __shfl_sync(FULL, aq_pre, r);
            float akv = ok ? g_ak[r * N_NODES + s] : 0.f;
            float lg = aqv + akv;
            lg = lg > 0.f ? lg : 0.2f * lg;
            m = fmaxf(m, ok ? lg : -INFINITY);
        }
#pragma unroll
        for (int o = 16; o; o >>= 1) m = fmaxf(m, __shfl_xor_sync(FULL, m, o));
        for (int i = start; i < end; i++) {
            int esr = g_esr[i];                 // warp-uniform load
            int s = esr & 0xffff, r = esr >> 16;
            float aqv = __shfl_sync(FULL, aq_pre, r);
            float lg = aqv + g_ak[r * N_NODES + s];
            lg = lg > 0.f ? lg : 0.2f * lg;
            float w = expf(lg - m);
            den += (lane == 0) ? w : 0.f;
            uint2 p0 = ((const uint2*)(g_xwh + ((size_t)r * N_NODES + s) * F))[lane];
            float2 a01 = __half22float2(*(__half2*)&p0.x);
            float2 a23 = __half22float2(*(__half2*)&p0.y);
            acc.x += w * a01.x; acc.y += w * a01.y;
            acc.z += w * a23.x; acc.w += w * a23.y;
        }
#pragma unroll
        for (int o = 16; o; o >>= 1) den += __shfl_xor_sync(FULL, den, o);
    }

    float inv = 1.0f / (den + 1e-16f);
    float4 bs = ((const float4*)bias)[lane];
    float4 o4;
    o4.x = fmaxf(acc.x * inv + bs.x, 0.f);
    o4.y = fmaxf(acc.y * inv + bs.y, 0.f);
    o4.z = fmaxf(acc.z * inv + bs.z, 0.f);
    o4.w = fmaxf(acc.w * inv + bs.w, 0.f);
    if (write_half) {
        __half2 h0 = __floats2half2_rn(o4.x, o4.y);
        __half2 h1 = __floats2half2_rn(o4.z, o4.w);
        uint2 p; p.x = *(unsigned*)&h0; p.y = *(unsigned*)&h1;
        ((uint2*)(g_hh + (size_t)n * F))[lane] = p;
    } else {
        ((float4*)(outf + (size_t)n * F))[lane] = o4;
    }
}

// ---------------- launch ----------------
extern "C" void kernel_launch(void* const* d_in, const int* in_sizes, int n_in,
                              void* d_out, int out_size) {
    const float* x    = (const float*)d_in[0];
    const float* W    = (const float*)d_in[1];
    const float* attq = (const float*)d_in[2];
    const float* attk = (const float*)d_in[3];
    const float* bias = (const float*)d_in[4];
    const int*   ei   = (const int*)d_in[5];
    const int*   et   = (const int*)d_in[6];
    float* out = (float*)d_out;

    // CSR by dst: layer-invariant, build once per call
    k_csr0   <<<(N_NODES + 255) / 256, 256>>>();
    k_hist   <<<(N_EDGES + 255) / 256, 256>>>(ei);
    k_scan   <<<1, 1024>>>();
    k_scatter<<<(N_EDGES + 255) / 256, 256>>>(ei, et);
    k_cvt    <<<(N_NODES * F / 4 + 255) / 256, 256>>>(x);

    for (int l = 0; l < 2; l++) {
        const float* Wl = W + (size_t)l * R * F * F;
        const float* ql = attq + (size_t)l * F;
        const float* kl = attk + (size_t)l * F;
        const float* bl = bias + (size_t)l * F;

        k_gemm<<<dim3((N_NODES + 127) / 128, R), 256>>>(Wl, ql, kl);
        k_attn<<<(N_NODES * 32 + 255) / 256, 256>>>(bl, out, l == 0 ? 1 : 0);
    }
}